// round 1
// baseline (speedup 1.0000x reference)
#include <cuda_runtime.h>
#include <math.h>

// ---------------------------------------------------------------------------
// Problem constants
// ---------------------------------------------------------------------------
#define BATCH   4
#define C       256
#define HQ      64
#define WQ      64
#define HW      4096            // HQ*WQ
#define HEADS   8
#define LEVELS  4
#define POINTS  4
#define HD      32              // C / HEADS
#define BN_EPS  1e-5f

// per-level spatial sizes: 64,32,16,8 ; pixel counts 4096,1024,256,64
#define VSTR    1392640         // 5440*256 floats per batch (all levels, channel-last)
// level offsets (in floats) inside one batch of g_v
__device__ __constant__ int c_voff[4] = {0, 1048576, 1310720, 1376256};

// ---------------------------------------------------------------------------
// Scratch (device globals — no allocation allowed)
// ---------------------------------------------------------------------------
__device__ float g_q     [BATCH * C * HW];     // q projection        (B,C,HW)
__device__ float g_off   [BATCH * 256 * HW];   // raw offset conv out (B,256,HW)
__device__ float g_logits[BATCH * 128 * HW];   // raw attn conv out   (B,128,HW)
__device__ float g_v     [BATCH * VSTR];       // values, channel-last (B, sum_l P_l, C)
__device__ float g_att   [BATCH * C * HW];     // attention output    (B,C,HW)

// ---------------------------------------------------------------------------
// SGEMM: Y[b] = W (256xK=256) @ X[b] (256 x N)
//   MODE 0: plain row-major store          Y[m*N+n]
//   MODE 1: transposed (channel-last) store Y[n*256+m]
//   MODE 2: fused epilogue: +query residual, BN, SiLU   (N must be 4096)
// BM=128, BN=64, BK=16, 256 threads, 8x4 microtile
// ---------------------------------------------------------------------------
template<int MODE>
__global__ __launch_bounds__(256)
void gemm256(const float* __restrict__ Wm, const float* __restrict__ X,
             float* __restrict__ Y, int N, long xStride, long yStride,
             const float* __restrict__ resid,
             const float* __restrict__ gamma, const float* __restrict__ beta,
             const float* __restrict__ mean,  const float* __restrict__ var)
{
    const int K = 256;
    __shared__ float As[16][128];
    __shared__ float Bs[16][64];

    const int b   = blockIdx.z;
    const float* Xb = X + (long)b * xStride;
    float*       Yb = Y + (long)b * yStride;
    const int m0  = blockIdx.y * 128;
    const int n0  = blockIdx.x * 64;
    const int tid = threadIdx.x;
    const int rt  = tid >> 4;     // 0..15  -> 8 rows each
    const int ct  = tid & 15;     // 0..15  -> 4 cols each

    float acc[8][4];
#pragma unroll
    for (int i = 0; i < 8; i++)
#pragma unroll
        for (int j = 0; j < 4; j++) acc[i][j] = 0.f;

    const int ra = tid >> 2;            // 0..63
    const int kq = (tid & 3) * 4;       // 0,4,8,12
    const int kb = tid >> 4;            // 0..15
    const int nq = (tid & 15) * 4;      // 0..60

    for (int k0 = 0; k0 < K; k0 += 16) {
#pragma unroll
        for (int p = 0; p < 2; p++) {
            float4 a = *(const float4*)&Wm[(m0 + p * 64 + ra) * K + k0 + kq];
            As[kq + 0][p * 64 + ra] = a.x;
            As[kq + 1][p * 64 + ra] = a.y;
            As[kq + 2][p * 64 + ra] = a.z;
            As[kq + 3][p * 64 + ra] = a.w;
        }
        *(float4*)&Bs[kb][nq] = *(const float4*)&Xb[(long)(k0 + kb) * N + n0 + nq];
        __syncthreads();

#pragma unroll
        for (int k = 0; k < 16; k++) {
            float4 a0 = *(const float4*)&As[k][rt * 8];
            float4 a1 = *(const float4*)&As[k][rt * 8 + 4];
            float4 bb = *(const float4*)&Bs[k][ct * 4];
            float av[8] = {a0.x, a0.y, a0.z, a0.w, a1.x, a1.y, a1.z, a1.w};
            float bv[4] = {bb.x, bb.y, bb.z, bb.w};
#pragma unroll
            for (int i = 0; i < 8; i++)
#pragma unroll
                for (int j = 0; j < 4; j++)
                    acc[i][j] = fmaf(av[i], bv[j], acc[i][j]);
        }
        __syncthreads();
    }

    if (MODE == 0) {
#pragma unroll
        for (int i = 0; i < 8; i++) {
            int m = m0 + rt * 8 + i;
            float4 o = make_float4(acc[i][0], acc[i][1], acc[i][2], acc[i][3]);
            *(float4*)&Yb[(long)m * N + n0 + ct * 4] = o;
        }
    } else if (MODE == 1) {
#pragma unroll
        for (int j = 0; j < 4; j++) {
            int n = n0 + ct * 4 + j;
            float4 t0 = make_float4(acc[0][j], acc[1][j], acc[2][j], acc[3][j]);
            float4 t1 = make_float4(acc[4][j], acc[5][j], acc[6][j], acc[7][j]);
            *(float4*)&Yb[n * 256 + m0 + rt * 8]     = t0;
            *(float4*)&Yb[n * 256 + m0 + rt * 8 + 4] = t1;
        }
    } else { // MODE 2: +residual, BN, SiLU
#pragma unroll
        for (int i = 0; i < 8; i++) {
            int m = m0 + rt * 8 + i;
            float g  = gamma[m] * rsqrtf(var[m] + BN_EPS);
            float mn = mean[m];
            float bt = beta[m];
            const float4 qv = *(const float4*)&resid[((long)b * 256 + m) * 4096 + n0 + ct * 4];
            float vv[4] = {qv.x, qv.y, qv.z, qv.w};
            float ov[4];
#pragma unroll
            for (int j = 0; j < 4; j++) {
                float x  = acc[i][j] + vv[j];
                float xn = (x - mn) * g + bt;
                ov[j] = xn / (1.f + expf(-xn));
            }
            *(float4*)&Yb[(long)m * N + n0 + ct * 4] =
                make_float4(ov[0], ov[1], ov[2], ov[3]);
        }
    }
}

// ---------------------------------------------------------------------------
// Direct 3x3 SAME conv on 64x64, C=256 input channels.
// Block: 64 output channels x (8 rows x 32 cols) pixels.
// Thread (to=tid>>5, tp=tid&31): 8 oc x 8 rows x 1 col.
// ---------------------------------------------------------------------------
__global__ __launch_bounds__(256)
void conv3x3_kernel(const float* __restrict__ x, const float* __restrict__ wgt,
                    const float* __restrict__ bias, float* __restrict__ y, int OC)
{
    __shared__ float xs[8][10][34];   // 8 input chans x (8+2) rows x (32+2) cols
    __shared__ float ws[64][72];      // 64 oc x (8 ic * 9 taps)

    const int b      = blockIdx.z;
    const int ocbase = blockIdx.y * 64;
    const int tx = blockIdx.x & 1;
    const int ty = blockIdx.x >> 1;
    const int c0 = tx * 32;
    const int r0 = ty * 8;
    const int tid = threadIdx.x;
    const int to = tid >> 5;   // 0..7
    const int tp = tid & 31;   // 0..31

    float acc[8][8];
#pragma unroll
    for (int i = 0; i < 8; i++)
#pragma unroll
        for (int r = 0; r < 8; r++) acc[i][r] = 0.f;

    const float* xb = x + (long)b * C * HW;

    for (int cb = 0; cb < C; cb += 8) {
        // load input patch (zero-padded SAME)
        for (int i = tid; i < 8 * 10 * 34; i += 256) {
            int ck  = i / 340;
            int rem = i % 340;
            int rr  = rem / 34;
            int cc  = rem % 34;
            int gh = r0 - 1 + rr;
            int gw = c0 - 1 + cc;
            float v = 0.f;
            if (gh >= 0 && gh < 64 && gw >= 0 && gw < 64)
                v = xb[((cb + ck) * 64 + gh) * 64 + gw];
            xs[ck][rr][cc] = v;
        }
        // load weights
        for (int i = tid; i < 64 * 72; i += 256) {
            int oc = i / 72;
            int t  = i % 72;
            ws[oc][t] = wgt[((ocbase + oc) * C + cb + t / 9) * 9 + (t % 9)];
        }
        __syncthreads();

        for (int ck = 0; ck < 8; ck++) {
#pragma unroll
            for (int tap = 0; tap < 9; tap++) {
                const int dy = tap / 3, dx = tap % 3;
                float xr[8];
#pragma unroll
                for (int r = 0; r < 8; r++) xr[r] = xs[ck][r + dy][tp + dx];
#pragma unroll
                for (int i = 0; i < 8; i++) {
                    float wv = ws[to * 8 + i][ck * 9 + tap];
#pragma unroll
                    for (int r = 0; r < 8; r++)
                        acc[i][r] = fmaf(wv, xr[r], acc[i][r]);
                }
            }
        }
        __syncthreads();
    }

#pragma unroll
    for (int i = 0; i < 8; i++) {
        int oc = ocbase + to * 8 + i;
        float bs = bias[oc];
#pragma unroll
        for (int r = 0; r < 8; r++)
            y[(((long)b * OC + oc) * 64 + r0 + r) * 64 + c0 + tp] = acc[i][r] + bs;
    }
}

// ---------------------------------------------------------------------------
// Deformable sampling. One warp per (b, head, pixel).
// Lanes 0..15 own (level,point) scalars (softmax weight + tanh offsets),
// all 32 lanes own one of the HD=32 channels for the gathers.
// ---------------------------------------------------------------------------
__global__ __launch_bounds__(256)
void sample_kernel(const float* __restrict__ off, const float* __restrict__ logits,
                   const float* __restrict__ v, float* __restrict__ att)
{
    const int warp = threadIdx.x >> 5;
    const int lane = threadIdx.x & 31;
    const int pix  = blockIdx.x * 8 + warp;        // 0..4095
    const int h    = blockIdx.y;
    const int b    = blockIdx.z;

    const int ph = pix >> 6;
    const int pw = pix & 63;
    const float refx = -1.f + 2.f * (float)pw / 63.f;
    const float refy = -1.f + 2.f * (float)ph / 63.f;

    // lanes 0..15: per-(lvl,pt) logit + offsets
    float lg = -INFINITY, ox = 0.f, oy = 0.f;
    if (lane < 16) {
        lg = logits[((b * 128 + h * 16 + lane) * HW) + pix];
        ox = tanhf(off[((b * 256 + h * 32 + 2 * lane    ) * HW) + pix]) * 0.25f;
        oy = tanhf(off[((b * 256 + h * 32 + 2 * lane + 1) * HW) + pix]) * 0.25f;
    }
    // softmax across the 16 (lvl,pt) entries
    float mx = lg;
#pragma unroll
    for (int s = 16; s > 0; s >>= 1)
        mx = fmaxf(mx, __shfl_xor_sync(0xFFFFFFFFu, mx, s));
    float e = (lane < 16) ? expf(lg - mx) : 0.f;
    float sum = e;
#pragma unroll
    for (int s = 16; s > 0; s >>= 1)
        sum += __shfl_xor_sync(0xFFFFFFFFu, sum, s);
    float wgt = e / sum;

    const float* vb = v + (long)b * VSTR + h * 32 + lane;

    float acc = 0.f;
#pragma unroll
    for (int i = 0; i < 16; i++) {
        const int lvl = i >> 2;
        const int sz  = 64 >> lvl;
        float aw = __shfl_sync(0xFFFFFFFFu, wgt, i);
        float gx = refx + __shfl_sync(0xFFFFFFFFu, ox, i);
        float gy = refy + __shfl_sync(0xFFFFFFFFu, oy, i);

        float xf = (gx + 1.f) * 0.5f * (float)(sz - 1);
        float yf = (gy + 1.f) * 0.5f * (float)(sz - 1);
        float x0f = floorf(xf), y0f = floorf(yf);
        int x0 = (int)x0f, y0 = (int)y0f;
        int x1 = x0 + 1,  y1 = y0 + 1;
        float wx1 = xf - x0f, wx0 = 1.f - wx1;
        float wy1 = yf - y0f, wy0 = 1.f - wy1;

        const float* vl = vb + c_voff[lvl];
        if (x0 >= 0 && x0 < sz && y0 >= 0 && y0 < sz)
            acc = fmaf(aw * wx0 * wy0, vl[(y0 * sz + x0) * 256], acc);
        if (x1 >= 0 && x1 < sz && y0 >= 0 && y0 < sz)
            acc = fmaf(aw * wx1 * wy0, vl[(y0 * sz + x1) * 256], acc);
        if (x0 >= 0 && x0 < sz && y1 >= 0 && y1 < sz)
            acc = fmaf(aw * wx0 * wy1, vl[(y1 * sz + x0) * 256], acc);
        if (x1 >= 0 && x1 < sz && y1 >= 0 && y1 < sz)
            acc = fmaf(aw * wx1 * wy1, vl[(y1 * sz + x1) * 256], acc);
    }

    att[((b * 256 + h * 32 + lane) * HW) + pix] = acc;
}

// ---------------------------------------------------------------------------
// Launch
// ---------------------------------------------------------------------------
extern "C" void kernel_launch(void* const* d_in, const int* in_sizes, int n_in,
                              void* d_out, int out_size)
{
    const float* query  = (const float*)d_in[0];
    const float* feat0  = (const float*)d_in[1];
    const float* feat1  = (const float*)d_in[2];
    const float* feat2  = (const float*)d_in[3];
    const float* feat3  = (const float*)d_in[4];
    const float* q_w    = (const float*)d_in[5];
    const float* v_w    = (const float*)d_in[6];
    const float* out_w  = (const float*)d_in[7];
    const float* off_w  = (const float*)d_in[8];
    const float* off_b  = (const float*)d_in[9];
    const float* attn_w = (const float*)d_in[10];
    const float* attn_b = (const float*)d_in[11];
    const float* bn_g   = (const float*)d_in[12];
    const float* bn_b   = (const float*)d_in[13];
    const float* bn_m   = (const float*)d_in[14];
    const float* bn_v   = (const float*)d_in[15];
    float* out = (float*)d_out;

    void *p_q, *p_off, *p_log, *p_v, *p_att;
    cudaGetSymbolAddress(&p_q,   g_q);
    cudaGetSymbolAddress(&p_off, g_off);
    cudaGetSymbolAddress(&p_log, g_logits);
    cudaGetSymbolAddress(&p_v,   g_v);
    cudaGetSymbolAddress(&p_att, g_att);
    float* gq   = (float*)p_q;
    float* goff = (float*)p_off;
    float* glog = (float*)p_log;
    float* gv   = (float*)p_v;
    float* gatt = (float*)p_att;

    // 1. q projection
    gemm256<0><<<dim3(64, 2, BATCH), 256>>>(q_w, query, gq, HW,
                                            (long)C * HW, (long)C * HW,
                                            nullptr, nullptr, nullptr, nullptr, nullptr);

    // 2. value projections per level (channel-last output)
    const float* feats[4] = {feat0, feat1, feat2, feat3};
    const int    NL[4]    = {4096, 1024, 256, 64};
    const int    VOFF[4]  = {0, 1048576, 1310720, 1376256};
    for (int l = 0; l < 4; l++) {
        gemm256<1><<<dim3(NL[l] / 64, 2, BATCH), 256>>>(
            v_w + l * C * C, feats[l], gv + VOFF[l], NL[l],
            (long)C * NL[l], (long)VSTR,
            nullptr, nullptr, nullptr, nullptr, nullptr);
    }

    // 3. convs on q
    conv3x3_kernel<<<dim3(16, 4, BATCH), 256>>>(gq, off_w,  off_b,  goff, 256);
    conv3x3_kernel<<<dim3(16, 2, BATCH), 256>>>(gq, attn_w, attn_b, glog, 128);

    // 4. deformable sampling
    sample_kernel<<<dim3(512, HEADS, BATCH), 256>>>(goff, glog, gv, gatt);

    // 5. output projection + residual + BN + SiLU
    gemm256<2><<<dim3(64, 2, BATCH), 256>>>(out_w, gatt, out, HW,
                                            (long)C * HW, (long)C * HW,
                                            query, bn_g, bn_b, bn_m, bn_v);
}

// round 3
// speedup vs baseline: 2.2822x; 2.2822x over previous
#include <cuda_runtime.h>
#include <math.h>
#include <stdint.h>

// ---------------------------------------------------------------------------
// Problem constants
// ---------------------------------------------------------------------------
#define BATCH   4
#define C       256
#define HW      4096
#define HEADS   8
#define BN_EPS  1e-5f
#define VSTR    (5440*256)      // per-batch floats, all levels channel-last

__device__ __constant__ int c_voff[4] = {0, 1048576, 1310720, 1376256};

// ---------------------------------------------------------------------------
// Scratch (device globals)
// ---------------------------------------------------------------------------
__device__ float g_qT [BATCH * HW * C];
__device__ float g_fT [BATCH * VSTR];
__device__ float g_q  [BATCH * HW * C];
__device__ float g_v  [BATCH * VSTR];
__device__ float g_cv [BATCH * HW * 384];
__device__ float g_att[BATCH * HW * C];
__device__ float g_Wc [384 * 2304];
__device__ float g_wr [6 * 65536];
__device__ float g_cb [384];
__device__ float g_bns[256], g_bnb[256];

// ---------------------------------------------------------------------------
// Helpers
// ---------------------------------------------------------------------------
__device__ __forceinline__ uint32_t smem_u32(const void* p) {
    uint32_t a;
    asm("{ .reg .u64 t; cvta.to.shared.u64 t, %1; cvt.u32.u64 %0, t; }"
        : "=r"(a) : "l"(p));
    return a;
}
__device__ __forceinline__ float rtf32(float x) {
    uint32_t r;
    asm("cvt.rna.tf32.f32 %0, %1;" : "=r"(r) : "f"(x));
    return __uint_as_float(r);
}
__device__ __forceinline__ void cp16(uint32_t dst, const float* src, bool v) {
    int sz = v ? 16 : 0;
    asm volatile("cp.async.cg.shared.global [%0], [%1], 16, %2;\n"
                 :: "r"(dst), "l"(src), "r"(sz) : "memory");
}
__device__ __forceinline__ void cp_commit() {
    asm volatile("cp.async.commit_group;\n" ::: "memory");
}
__device__ __forceinline__ void cp_wait(int n) {
    if (n == 0) asm volatile("cp.async.wait_group 0;\n" ::: "memory");
    else        asm volatile("cp.async.wait_group 1;\n" ::: "memory");
}
__device__ __forceinline__ void mma_tf32(float* c, const uint32_t* a, const uint32_t* b) {
    asm volatile(
        "mma.sync.aligned.m16n8k8.row.col.f32.tf32.tf32.f32 "
        "{%0,%1,%2,%3}, {%4,%5,%6,%7}, {%8,%9}, {%0,%1,%2,%3};"
        : "+f"(c[0]), "+f"(c[1]), "+f"(c[2]), "+f"(c[3])
        : "r"(a[0]), "r"(a[1]), "r"(a[2]), "r"(a[3]), "r"(b[0]), "r"(b[1]));
}

// smem geometry: A/B tiles stored [row][k] with 36-float stride (conflict-free)
#define ASTR     36
#define STG_F    (128 * ASTR)         // floats per tile stage
#define B_BASE   (2 * STG_F)          // B tiles after 2 A stages
#define DSMEM_SZ (4 * STG_F * 4)      // 73728 bytes

// ---------------------------------------------------------------------------
// tf32 mma.sync GEMM:  D[128 pix][128 oc] = sum_k A[pix][k] * B[oc][k]
//   CONVA=1: A = implicit im2col of channel-last q (k = tap*256 + ic)
//   EPI=0:   channel-last store (+bias, optional tf32 rounding)
//   EPI=1:   out-proj: +residual, BN, SiLU, channel-first store
// Block 256 threads = 8 warps (2 m x 4 n), warp tile 64x32, BK=32.
// ---------------------------------------------------------------------------
template<int CONVA, int EPI>
__global__ __launch_bounds__(256, 1)
void mm_tf32(const float* __restrict__ A, long aB,
             const float* __restrict__ Bw,
             float* __restrict__ Y, long yB, int ldY,
             int M_act, int NK,
             const float* __restrict__ bias, int roundOut,
             const float* __restrict__ resid,
             const float* __restrict__ bns, const float* __restrict__ bnb)
{
    extern __shared__ float sm[];

    const int b    = blockIdx.z;
    const int m0   = blockIdx.x * 128;
    const int n0   = blockIdx.y * 128;
    const int tid  = threadIdx.x;
    const int wid  = tid >> 5;
    const int lane = tid & 31;
    const int wm   = wid >> 2;          // 0..1 -> m offset 64
    const int wn   = wid & 3;           // 0..3 -> n offset 32
    const int gid  = lane >> 2;
    const int tig  = lane & 3;

    const float* Ab = A + (long)b * aB;
    const int K = NK * 32;
    const uint32_t smb = smem_u32(sm);

    float acc[4][4][4];
#pragma unroll
    for (int mt = 0; mt < 4; mt++)
#pragma unroll
        for (int nt = 0; nt < 4; nt++)
#pragma unroll
            for (int r = 0; r < 4; r++) acc[mt][nt][r] = 0.f;

    auto load_stage = [&](int s) {
        const int buf = s & 1;
        const int k0g = s * 32;
        const int tap = CONVA ? (s >> 3) : 0;
        const int ic0 = CONVA ? ((s & 7) * 32) : 0;
        const int dy = tap / 3 - 1, dx = tap % 3 - 1;
#pragma unroll
        for (int i = 0; i < 4; i++) {
            int ci  = i * 256 + tid;
            int row = ci >> 3;
            int kc  = ci & 7;
            uint32_t dstA = smb + (buf * STG_F + row * ASTR + kc * 4) * 4;
            if (CONVA) {
                int p  = m0 + row;
                int py = (p >> 6) + dy, px = (p & 63) + dx;
                bool v = (py >= 0) & (py < 64) & (px >= 0) & (px < 64);
                const float* src = v ? (Ab + ((long)((py << 6) + px)) * 256 + ic0 + kc * 4)
                                     : Ab;
                cp16(dstA, src, v);
            } else {
                bool v = (m0 + row) < M_act;
                const float* src = v ? (Ab + (long)(m0 + row) * K + k0g + kc * 4) : Ab;
                cp16(dstA, src, v);
            }
            uint32_t dstB = smb + (B_BASE + buf * STG_F + row * ASTR + kc * 4) * 4;
            cp16(dstB, Bw + (long)(n0 + row) * K + k0g + kc * 4, true);
        }
    };

    load_stage(0); cp_commit();

    for (int s = 0; s < NK; s++) {
        const int buf = s & 1;
        const bool more = (s + 1) < NK;
        if (more) { load_stage(s + 1); cp_commit(); }
        cp_wait(more ? 1 : 0);
        __syncthreads();

        const uint32_t* sA = (const uint32_t*)(sm + buf * STG_F);
        const uint32_t* sB = (const uint32_t*)(sm + B_BASE + buf * STG_F);
#pragma unroll
        for (int kk = 0; kk < 4; kk++) {
            const int k0 = kk * 8;
            uint32_t af[4][4];
#pragma unroll
            for (int mt = 0; mt < 4; mt++) {
                int r = wm * 64 + mt * 16 + gid;
                af[mt][0] = sA[r * ASTR + k0 + tig];
                af[mt][1] = sA[(r + 8) * ASTR + k0 + tig];
                af[mt][2] = sA[r * ASTR + k0 + tig + 4];
                af[mt][3] = sA[(r + 8) * ASTR + k0 + tig + 4];
            }
            uint32_t bf[4][2];
#pragma unroll
            for (int nt = 0; nt < 4; nt++) {
                int n = wn * 32 + nt * 8 + gid;
                bf[nt][0] = sB[n * ASTR + k0 + tig];
                bf[nt][1] = sB[n * ASTR + k0 + tig + 4];
            }
#pragma unroll
            for (int mt = 0; mt < 4; mt++)
#pragma unroll
                for (int nt = 0; nt < 4; nt++)
                    mma_tf32(acc[mt][nt], af[mt], bf[nt]);
        }
        __syncthreads();
    }

    // ---- epilogue ----
    if (EPI == 0) {
        float* Yb = Y + (long)b * yB;
#pragma unroll
        for (int mt = 0; mt < 4; mt++) {
            int r0 = m0 + wm * 64 + mt * 16 + gid;
#pragma unroll
            for (int nt = 0; nt < 4; nt++) {
                int col = n0 + wn * 32 + nt * 8 + tig * 2;
                float bx = bias ? bias[col]     : 0.f;
                float by = bias ? bias[col + 1] : 0.f;
#pragma unroll
                for (int h = 0; h < 2; h++) {
                    int r = r0 + h * 8;
                    if (r < M_act) {
                        float vx = acc[mt][nt][2 * h]     + bx;
                        float vy = acc[mt][nt][2 * h + 1] + by;
                        if (roundOut) { vx = rtf32(vx); vy = rtf32(vy); }
                        *(float2*)&Yb[(long)r * ldY + col] = make_float2(vx, vy);
                    }
                }
            }
        }
    } else {
        const float* qb = resid + (long)b * C * HW;
        float* yb = Y + (long)b * C * HW;
#pragma unroll
        for (int mt = 0; mt < 4; mt++) {
            int r0 = m0 + wm * 64 + mt * 16 + gid;
#pragma unroll
            for (int nt = 0; nt < 4; nt++) {
                int col = n0 + wn * 32 + nt * 8 + tig * 2;
#pragma unroll
                for (int h = 0; h < 2; h++) {
                    int r = r0 + h * 8;
                    if (r < M_act) {
#pragma unroll
                        for (int j = 0; j < 2; j++) {
                            int oc = col + j;
                            float x  = acc[mt][nt][2 * h + j] + qb[(long)oc * HW + r];
                            float xn = x * bns[oc] + bnb[oc];
                            yb[(long)oc * HW + r] = xn / (1.f + expf(-xn));
                        }
                    }
                }
            }
        }
    }
}

// ---------------------------------------------------------------------------
// Transpose (C=256, P) -> (P, 256) with tf32 rounding
// ---------------------------------------------------------------------------
__global__ __launch_bounds__(256)
void transpose_rt(const float* __restrict__ in, float* __restrict__ out,
                  int P, long inB, long outB)
{
    __shared__ float t[32][33];
    const int b = blockIdx.z;
    const float* I = in + (long)b * inB;
    float* O = out + (long)b * outB;
    const int p0 = blockIdx.x * 32, c0 = blockIdx.y * 32;
    const int tx = threadIdx.x & 31, ty = threadIdx.x >> 5;
#pragma unroll
    for (int i = 0; i < 32; i += 8)
        t[ty + i][tx] = I[(long)(c0 + ty + i) * P + p0 + tx];
    __syncthreads();
#pragma unroll
    for (int i = 0; i < 32; i += 8)
        O[(long)(p0 + ty + i) * 256 + c0 + tx] = rtf32(t[tx][ty + i]);
}

// ---------------------------------------------------------------------------
// Weight prep
// ---------------------------------------------------------------------------
__global__ void prep_conv_w(const float* __restrict__ off_w, const float* __restrict__ attn_w,
                            const float* __restrict__ off_b, const float* __restrict__ attn_b,
                            float* __restrict__ Wc, float* __restrict__ cb)
{
    int idx = blockIdx.x * 256 + threadIdx.x;
    if (idx < 384 * 2304) {
        int oc = idx / 2304, k = idx % 2304;
        int tap = k >> 8, ic = k & 255;
        float v = (oc < 256) ? off_w[(oc * 256 + ic) * 9 + tap]
                             : attn_w[((oc - 256) * 256 + ic) * 9 + tap];
        Wc[idx] = rtf32(v);
    }
    if (idx < 384) cb[idx] = (idx < 256) ? off_b[idx] : attn_b[idx - 256];
}

__global__ void prep_small(const float* __restrict__ qw, const float* __restrict__ vw,
                           const float* __restrict__ ow, float* __restrict__ wr,
                           const float* __restrict__ g, const float* __restrict__ be,
                           const float* __restrict__ mn, const float* __restrict__ va,
                           float* __restrict__ bns, float* __restrict__ bnb)
{
    int i = blockIdx.x * 256 + threadIdx.x;
    if (i < 65536)            wr[i] = rtf32(qw[i]);
    else if (i < 5 * 65536)   wr[i] = rtf32(vw[i - 65536]);
    else if (i < 6 * 65536)   wr[i] = rtf32(ow[i - 5 * 65536]);
    if (i < 256) {
        float s = g[i] * rsqrtf(va[i] + BN_EPS);
        bns[i] = s;
        bnb[i] = be[i] - mn[i] * s;
    }
}

// ---------------------------------------------------------------------------
// Deformable sampling (channel-last). One warp per (b, head, pixel).
// ---------------------------------------------------------------------------
__global__ __launch_bounds__(256)
void sample_kernel(const float* __restrict__ cv, const float* __restrict__ v,
                   float* __restrict__ att)
{
    const int warp = threadIdx.x >> 5;
    const int lane = threadIdx.x & 31;
    const int pix  = blockIdx.x * 8 + warp;
    const int h    = blockIdx.y;
    const int b    = blockIdx.z;

    const int ph = pix >> 6;
    const int pw = pix & 63;
    const float refx = -1.f + 2.f * (float)pw / 63.f;
    const float refy = -1.f + 2.f * (float)ph / 63.f;

    const float* cvp = cv + ((long)b * HW + pix) * 384;
    float lg = -INFINITY, ox = 0.f, oy = 0.f;
    if (lane < 16) {
        lg = cvp[256 + h * 16 + lane];
        ox = tanhf(cvp[h * 32 + 2 * lane    ]) * 0.25f;
        oy = tanhf(cvp[h * 32 + 2 * lane + 1]) * 0.25f;
    }
    float mx = lg;
#pragma unroll
    for (int s = 16; s > 0; s >>= 1)
        mx = fmaxf(mx, __shfl_xor_sync(0xFFFFFFFFu, mx, s));
    float e = (lane < 16) ? expf(lg - mx) : 0.f;
    float sum = e;
#pragma unroll
    for (int s = 16; s > 0; s >>= 1)
        sum += __shfl_xor_sync(0xFFFFFFFFu, sum, s);
    float wgt = e / sum;

    const float* vb = v + (long)b * VSTR + h * 32 + lane;

    float acc = 0.f;
#pragma unroll
    for (int i = 0; i < 16; i++) {
        const int lvl = i >> 2;
        const int sz  = 64 >> lvl;
        float aw = __shfl_sync(0xFFFFFFFFu, wgt, i);
        float gx = refx + __shfl_sync(0xFFFFFFFFu, ox, i);
        float gy = refy + __shfl_sync(0xFFFFFFFFu, oy, i);

        float xf = (gx + 1.f) * 0.5f * (float)(sz - 1);
        float yf = (gy + 1.f) * 0.5f * (float)(sz - 1);
        float x0f = floorf(xf), y0f = floorf(yf);
        int x0 = (int)x0f, y0 = (int)y0f;
        int x1 = x0 + 1,  y1 = y0 + 1;
        float wx1 = xf - x0f, wx0 = 1.f - wx1;
        float wy1 = yf - y0f, wy0 = 1.f - wy1;

        const float* vl = vb + c_voff[lvl];
        if (x0 >= 0 && x0 < sz && y0 >= 0 && y0 < sz)
            acc = fmaf(aw * wx0 * wy0, vl[(y0 * sz + x0) * 256], acc);
        if (x1 >= 0 && x1 < sz && y0 >= 0 && y0 < sz)
            acc = fmaf(aw * wx1 * wy0, vl[(y0 * sz + x1) * 256], acc);
        if (x0 >= 0 && x0 < sz && y1 >= 0 && y1 < sz)
            acc = fmaf(aw * wx0 * wy1, vl[(y1 * sz + x0) * 256], acc);
        if (x1 >= 0 && x1 < sz && y1 >= 0 && y1 < sz)
            acc = fmaf(aw * wx1 * wy1, vl[(y1 * sz + x1) * 256], acc);
    }

    att[((long)b * HW + pix) * 256 + h * 32 + lane] = rtf32(acc);
}

// ---------------------------------------------------------------------------
// Launch
// ---------------------------------------------------------------------------
extern "C" void kernel_launch(void* const* d_in, const int* in_sizes, int n_in,
                              void* d_out, int out_size)
{
    const float* query  = (const float*)d_in[0];
    const float* feat0  = (const float*)d_in[1];
    const float* feat1  = (const float*)d_in[2];
    const float* feat2  = (const float*)d_in[3];
    const float* feat3  = (const float*)d_in[4];
    const float* q_w    = (const float*)d_in[5];
    const float* v_w    = (const float*)d_in[6];
    const float* out_w  = (const float*)d_in[7];
    const float* off_w  = (const float*)d_in[8];
    const float* off_b  = (const float*)d_in[9];
    const float* attn_w = (const float*)d_in[10];
    const float* attn_b = (const float*)d_in[11];
    const float* bn_g   = (const float*)d_in[12];
    const float* bn_b   = (const float*)d_in[13];
    const float* bn_m   = (const float*)d_in[14];
    const float* bn_v   = (const float*)d_in[15];
    float* out = (float*)d_out;

    void *p;
    float *gqT, *gfT, *gq, *gv, *gcv, *gatt, *gWc, *gwr, *gcb, *gbns, *gbnb;
    cudaGetSymbolAddress(&p, g_qT);  gqT  = (float*)p;
    cudaGetSymbolAddress(&p, g_fT);  gfT  = (float*)p;
    cudaGetSymbolAddress(&p, g_q);   gq   = (float*)p;
    cudaGetSymbolAddress(&p, g_v);   gv   = (float*)p;
    cudaGetSymbolAddress(&p, g_cv);  gcv  = (float*)p;
    cudaGetSymbolAddress(&p, g_att); gatt = (float*)p;
    cudaGetSymbolAddress(&p, g_Wc);  gWc  = (float*)p;
    cudaGetSymbolAddress(&p, g_wr);  gwr  = (float*)p;
    cudaGetSymbolAddress(&p, g_cb);  gcb  = (float*)p;
    cudaGetSymbolAddress(&p, g_bns); gbns = (float*)p;
    cudaGetSymbolAddress(&p, g_bnb); gbnb = (float*)p;

    cudaFuncSetAttribute(mm_tf32<0,0>, cudaFuncAttributeMaxDynamicSharedMemorySize, DSMEM_SZ);
    cudaFuncSetAttribute(mm_tf32<1,0>, cudaFuncAttributeMaxDynamicSharedMemorySize, DSMEM_SZ);
    cudaFuncSetAttribute(mm_tf32<0,1>, cudaFuncAttributeMaxDynamicSharedMemorySize, DSMEM_SZ);

    // ---- prep ----
    prep_small<<<1536, 256>>>(q_w, v_w, out_w, gwr, bn_g, bn_b, bn_m, bn_v, gbns, gbnb);
    prep_conv_w<<<3456, 256>>>(off_w, attn_w, off_b, attn_b, gWc, gcb);

    transpose_rt<<<dim3(128, 8, BATCH), 256>>>(query, gqT, 4096, (long)C * HW, (long)HW * C);
    const float* feats[4] = {feat0, feat1, feat2, feat3};
    const int    NL[4]    = {4096, 1024, 256, 64};
    const int    VOFF[4]  = {0, 1048576, 1310720, 1376256};
    for (int l = 0; l < 4; l++)
        transpose_rt<<<dim3(NL[l] / 32, 8, BATCH), 256>>>(
            feats[l], gfT + VOFF[l], NL[l], (long)C * NL[l], (long)VSTR);

    // ---- q projection (round output: it feeds the conv GEMM) ----
    mm_tf32<0,0><<<dim3(32, 2, BATCH), 256, DSMEM_SZ>>>(
        gqT, (long)HW * C, gwr, gq, (long)HW * C, 256, 4096, 8,
        nullptr, 1, nullptr, nullptr, nullptr);

    // ---- value projections ----
    for (int l = 0; l < 4; l++) {
        int mt = (NL[l] + 127) / 128;
        mm_tf32<0,0><<<dim3(mt, 2, BATCH), 256, DSMEM_SZ>>>(
            gfT + VOFF[l], (long)VSTR, gwr + (1 + l) * 65536,
            gv + VOFF[l], (long)VSTR, 256, NL[l], 8,
            nullptr, 0, nullptr, nullptr, nullptr);
    }

    // ---- both 3x3 convs as one implicit GEMM (N=384, K=2304) ----
    mm_tf32<1,0><<<dim3(32, 3, BATCH), 256, DSMEM_SZ>>>(
        gq, (long)HW * C, gWc, gcv, (long)HW * 384, 384, 4096, 72,
        gcb, 0, nullptr, nullptr, nullptr);

    // ---- deformable sampling ----
    sample_kernel<<<dim3(512, HEADS, BATCH), 256>>>(gcv, gv, gatt);

    // ---- output projection + residual + BN + SiLU (channel-first store) ----
    mm_tf32<0,1><<<dim3(32, 2, BATCH), 256, DSMEM_SZ>>>(
        gatt, (long)HW * C, gwr + 5 * 65536, out, (long)C * HW, 4096, 4096, 8,
        nullptr, 0, query, gbns, gbnb);
}